// round 10
// baseline (speedup 1.0000x reference)
#include <cuda_runtime.h>

#define KC 32
#define LC 64
#define HC 256
#define OC 32
#define BMAX 256
#define NMAX 100000
#define NB 128            // histogram / scatter blocks
#define CPG 4             // CTAs per graph
#define TN 8              // nodes per warp
#define CHUNK 64          // nodes per CTA chunk
#define HSTR 260          // padded h row stride (floats) -> conflict-free

#define ZW1_SMEM ((LC*HC + 4*LC) * 4)
// zw1s + w2e + ss + hsm (floats) + nids (ints)
#define MAIN_FLOATS (KC*HC + HC*OC + CHUNK*KC + 8*4*HSTR)
#define MAIN_SMEM (MAIN_FLOATS*4 + CHUNK*4)

typedef unsigned long long u64;

__device__ __forceinline__ u64 fma2(u64 a, u64 b, u64 c) {
    u64 d;
    asm("fma.rn.f32x2 %0, %1, %2, %3;" : "=l"(d) : "l"(a), "l"(b), "l"(c));
    return d;
}
__device__ __forceinline__ u64 pack2(float lo, float hi) {
    u64 d;
    asm("mov.b64 %0, {%1, %2};" : "=l"(d) : "f"(lo), "f"(hi));
    return d;
}
__device__ __forceinline__ void unpack2(u64 v, float& lo, float& hi) {
    asm("mov.b64 {%0, %1}, %2;" : "=f"(lo), "=f"(hi) : "l"(v));
}

// ---------------- device scratch ------------------------------------------
__device__ float g_zw1[BMAX * KC * HC];    // 8 MB: z @ W1
__device__ float g_w2e[HC * OC];           // W2 repacked [jp2][jj][og][4]
__device__ int   g_perm[NMAX];
__device__ int   g_hist[BMAX];
__device__ int   g_cnt[BMAX];
__device__ int   g_binstart[BMAX];
__device__ int   g_bh[NB * BMAX];          // per-block histograms
__device__ int   g_bhoff[NB * BMAX];       // per-(block,bin) base offsets

// ---------------- 1. zW1 = z @ W1 (+ fused W2 repack in extra blocks) -----
__global__ void zw1_kernel(const float* __restrict__ z,
                           const float* __restrict__ W1,
                           const float* __restrict__ W2, int zw1_blocks) {
    int tid = threadIdx.x;
    if ((int)blockIdx.x >= zw1_blocks) {
        // W2 repack: flat float idx = jp2*128 + jj*32 + og*4 + oo
        int idx = (blockIdx.x - zw1_blocks) * 256 + tid;   // float4 index 0..2047
        int jp2 = idx >> 5;
        int rem = idx & 31;                // jj*8 + og
        int jj = rem >> 3, og = rem & 7;
        int j = jp2 * 4 + jj, o0 = og * 4;
        float4 v;
        v.x = W2[j * OC + o0 + 0];
        v.y = W2[j * OC + o0 + 1];
        v.z = W2[j * OC + o0 + 2];
        v.w = W2[j * OC + o0 + 3];
        ((float4*)g_w2e)[idx] = v;
        return;
    }
    extern __shared__ __align__(16) float sm[];
    float* w1s = sm;              // LC*HC
    float* zs  = sm + LC * HC;    // 4*LC

    for (int i = tid; i < (LC * HC) / 4; i += 256)
        ((float4*)w1s)[i] = ((const float4*)W1)[i];

    int rows = zw1_blocks * 16;   // == B*KC
    int row0 = blockIdx.x * 16;
    for (int g = 0; g < 4; g++) {
        int rbase = row0 + g * 4;
        __syncthreads();
        int rr = tid >> 6, ll = tid & 63;
        if (rbase + rr < rows)
            zs[rr * LC + ll] = z[(size_t)(rbase + rr) * LC + ll];
        __syncthreads();

        float a0 = 0.f, a1 = 0.f, a2 = 0.f, a3 = 0.f;
        #pragma unroll
        for (int l = 0; l < LC; l++) {
            float w = w1s[l * HC + tid];
            a0 += zs[0 * LC + l] * w;
            a1 += zs[1 * LC + l] * w;
            a2 += zs[2 * LC + l] * w;
            a3 += zs[3 * LC + l] * w;
        }
        if (rbase + 3 < rows) {
            g_zw1[(size_t)(rbase + 0) * HC + tid] = a0;
            g_zw1[(size_t)(rbase + 1) * HC + tid] = a1;
            g_zw1[(size_t)(rbase + 2) * HC + tid] = a2;
            g_zw1[(size_t)(rbase + 3) * HC + tid] = a3;
        }
    }
}

// ---------------- 2. per-block histogram + global histogram ---------------
__global__ void hist_kernel(const int* __restrict__ batch, int n, int B) {
    __shared__ int sh[BMAX];
    int tid = threadIdx.x, blk = blockIdx.x;
    sh[tid] = 0;
    __syncthreads();
    int span = (n + NB - 1) / NB;
    int lo = blk * span, hi = min(n, lo + span);
    for (int i = lo + tid; i < hi; i += 256) {
        int b = batch[i];
        if (b >= 0 && b < B) atomicAdd(&sh[b], 1);
    }
    __syncthreads();
    g_bh[blk * BMAX + tid] = sh[tid];
    if (sh[tid]) atomicAdd(&g_hist[tid], sh[tid]);
}

// ---------------- 3. bin scan; snapshot counts; re-zero global hist -------
__global__ void scan_kernel() {
    __shared__ int tmp[BMAX];
    int tid = threadIdx.x;
    int v0 = g_hist[tid];
    g_cnt[tid]  = v0;
    g_hist[tid] = 0;               // idempotent across graph replays
    tmp[tid] = v0;
    __syncthreads();
    for (int d = 1; d < BMAX; d <<= 1) {
        int v = (tid >= d) ? tmp[tid - d] : 0;
        __syncthreads();
        tmp[tid] += v;
        __syncthreads();
    }
    g_binstart[tid] = tmp[tid] - v0;
}

// ---------------- 3b. per-(block,bin) offsets ------------------------------
__global__ void blockoff_kernel() {
    int bin = threadIdx.x;         // one thread per bin
    int run = g_binstart[bin];
    for (int blk = 0; blk < NB; blk++) {
        g_bhoff[blk * BMAX + bin] = run;
        run += g_bh[blk * BMAX + bin];
    }
}

// ---------------- 4. scatter via SMEM cursors (no global atomics) ---------
__global__ void scatter_kernel(const int* __restrict__ batch, int n, int B) {
    __shared__ int cur[BMAX];
    int tid = threadIdx.x, blk = blockIdx.x;
    cur[tid] = g_bhoff[blk * BMAX + tid];
    __syncthreads();
    int span = (n + NB - 1) / NB;
    int lo = blk * span, hi = min(n, lo + span);
    for (int i = lo + tid; i < hi; i += 256) {
        int b = batch[i];
        if (b < 0 || b >= B) continue;
        int pos = atomicAdd(&cur[b], 1);    // smem atomic, spread addrs
        g_perm[pos] = i;
    }
}

// ---------------- 5. main fused kernel ------------------------------------
// CTA = (graph, chunk stride CPG). zW1[b] + repacked W2 resident in SMEM.
// h-stage: warp tile 8 nodes, lane owns 8 H-columns (4 u64 pairs).
// out-stage: 2 passes of 4 nodes; lane = (t=lane>>3, og=lane&7), o=og*4..+3;
// W2 reads are full-crossbar-BW LDS.128; h reads 4-address conflict-free.
__global__ __launch_bounds__(256, 2)
void main_kernel(const float* __restrict__ s,
                 const float* __restrict__ b1, const float* __restrict__ b2,
                 float* __restrict__ out, int B) {
    extern __shared__ __align__(16) float sm[];
    float* zw1s = sm;                      // 8192
    float* w2e  = zw1s + KC * HC;          // 8192
    float* ss   = w2e + HC * OC;           // CHUNK*KC = 2048
    float* hsm  = ss + CHUNK * KC;         // 8*4*HSTR = 8320
    int*   nids = (int*)(hsm + 8 * 4 * HSTR);   // CHUNK ints

    int tid = threadIdx.x;
    int b   = blockIdx.x % B;
    int c0  = blockIdx.x / B;
    int cnt = g_cnt[b];
    if (c0 * CHUNK >= cnt) return;
    int start = g_binstart[b];

    // prologue: linear float4 copies
    const float4* zw1g = (const float4*)(g_zw1 + (size_t)b * KC * HC);
    #pragma unroll
    for (int i = 0; i < 8; i++)
        ((float4*)zw1s)[tid + i * 256] = zw1g[tid + i * 256];
    #pragma unroll
    for (int i = 0; i < 8; i++)
        ((float4*)w2e)[tid + i * 256] = ((const float4*)g_w2e)[tid + i * 256];

    int w = tid >> 5, lane = tid & 31;
    int tp = lane >> 3, og = lane & 7;     // out-stage role
    float* hw = hsm + w * (4 * HSTR);

    // biases in registers (persist across chunks)
    u64 bp[4];
    {
        ulonglong2 p0 = *(const ulonglong2*)&b1[lane * 8];
        ulonglong2 p1 = *(const ulonglong2*)&b1[lane * 8 + 4];
        bp[0] = p0.x; bp[1] = p0.y; bp[2] = p1.x; bp[3] = p1.y;
    }
    float4 b2v = *(const float4*)&b2[og * 4];

    for (int c = c0; c * CHUNK < cnt; c += CPG) {
        int nbase = c * CHUNK;
        __syncthreads();                   // protect ss/nids/hsm reuse (+prologue)
        // stage nids + s rows: 512 float4, 2 per thread
        #pragma unroll
        for (int e = 0; e < 2; e++) {
            int idx = e * 256 + tid;
            int i = idx >> 3, q = idx & 7;
            int gi = nbase + i;
            int nid = (gi < cnt) ? g_perm[start + gi] : -1;
            if (q == 0) nids[i] = nid;
            float4 v = make_float4(0.f, 0.f, 0.f, 0.f);
            if (nid >= 0) v = ((const float4*)(s + (size_t)nid * KC))[q];
            ((float4*)(ss + i * KC))[q] = v;
        }
        __syncthreads();

        // ---- h-stage: lane owns j = lane*8..+7 ; 8 nodes per warp
        u64 ha[TN][4];
        #pragma unroll
        for (int t = 0; t < TN; t++) {
            ha[t][0] = bp[0]; ha[t][1] = bp[1];
            ha[t][2] = bp[2]; ha[t][3] = bp[3];
        }
        const float* ssw = ss + w * TN * KC;
        #pragma unroll 4
        for (int k = 0; k < KC; k++) {
            ulonglong2 wa = *(const ulonglong2*)&zw1s[k * HC + lane * 8];
            ulonglong2 wb = *(const ulonglong2*)&zw1s[k * HC + lane * 8 + 4];
            #pragma unroll
            for (int t = 0; t < TN; t++) {
                float sv = ssw[t * KC + k];        // broadcast
                u64 svp = pack2(sv, sv);
                ha[t][0] = fma2(svp, wa.x, ha[t][0]);
                ha[t][1] = fma2(svp, wa.y, ha[t][1]);
                ha[t][2] = fma2(svp, wb.x, ha[t][2]);
                ha[t][3] = fma2(svp, wb.y, ha[t][3]);
            }
        }

        // ---- out-stage: two passes of 4 nodes
        #pragma unroll
        for (int p = 0; p < 2; p++) {
            // relu + stage h for this pass (lane owns its 8 j's)
            #pragma unroll
            for (int t = 0; t < 4; t++) {
                int tt = p * 4 + t;
                float x, y;
                float* dst = hw + t * HSTR + lane * 8;
                unpack2(ha[tt][0], x, y); dst[0] = fmaxf(x,0.f); dst[1] = fmaxf(y,0.f);
                unpack2(ha[tt][1], x, y); dst[2] = fmaxf(x,0.f); dst[3] = fmaxf(y,0.f);
                unpack2(ha[tt][2], x, y); dst[4] = fmaxf(x,0.f); dst[5] = fmaxf(y,0.f);
                unpack2(ha[tt][3], x, y); dst[6] = fmaxf(x,0.f); dst[7] = fmaxf(y,0.f);
            }
            __syncwarp();

            u64 acc0 = 0ull, acc1 = 0ull;
            const float* hrow = hw + tp * HSTR;
            #pragma unroll 4
            for (int jp2 = 0; jp2 < HC / 4; jp2++) {
                float4 hv = *(const float4*)&hrow[jp2 * 4];      // 4 distinct addrs
                const float* wb4 = w2e + jp2 * 128 + og * 4;
                ulonglong2 w0 = *(const ulonglong2*)&wb4[0];     // jj=0: o-pairs
                ulonglong2 w1 = *(const ulonglong2*)&wb4[32];    // jj=1
                ulonglong2 w2 = *(const ulonglong2*)&wb4[64];    // jj=2
                ulonglong2 w3 = *(const ulonglong2*)&wb4[96];    // jj=3
                u64 h0 = pack2(hv.x, hv.x), h1 = pack2(hv.y, hv.y);
                u64 h2 = pack2(hv.z, hv.z), h3 = pack2(hv.w, hv.w);
                acc0 = fma2(h0, w0.x, acc0); acc1 = fma2(h0, w0.y, acc1);
                acc0 = fma2(h1, w1.x, acc0); acc1 = fma2(h1, w1.y, acc1);
                acc0 = fma2(h2, w2.x, acc0); acc1 = fma2(h2, w2.y, acc1);
                acc0 = fma2(h3, w3.x, acc0); acc1 = fma2(h3, w3.y, acc1);
            }
            int nid = nids[w * TN + p * 4 + tp];
            if (nid >= 0) {
                float4 r;
                unpack2(acc0, r.x, r.y);
                unpack2(acc1, r.z, r.w);
                r.x += b2v.x; r.y += b2v.y; r.z += b2v.z; r.w += b2v.w;
                *(float4*)(out + (size_t)nid * OC + og * 4) = r;
            }
            __syncwarp();
        }
    }
}

// ---------------- launch ---------------------------------------------------
extern "C" void kernel_launch(void* const* d_in, const int* in_sizes, int n_in,
                              void* d_out, int out_size) {
    const float* z     = (const float*)d_in[0];
    const float* s     = (const float*)d_in[1];
    const int*   batch = (const int*)d_in[2];   // JAX x64 disabled -> int32
    const float* W1    = (const float*)d_in[3];
    const float* b1    = (const float*)d_in[4];
    const float* W2    = (const float*)d_in[5];
    const float* b2    = (const float*)d_in[6];
    float*       out   = (float*)d_out;

    int n = in_sizes[2];
    int B = in_sizes[0] / (KC * LC);
    int zw1_blocks = (B * KC + 15) / 16;

    cudaFuncSetAttribute(zw1_kernel,
        cudaFuncAttributeMaxDynamicSharedMemorySize, ZW1_SMEM);
    cudaFuncSetAttribute(main_kernel,
        cudaFuncAttributeMaxDynamicSharedMemorySize, MAIN_SMEM);

    zw1_kernel<<<zw1_blocks + 8, 256, ZW1_SMEM>>>(z, W1, W2, zw1_blocks);
    hist_kernel<<<NB, 256>>>(batch, n, B);
    scan_kernel<<<1, BMAX>>>();
    blockoff_kernel<<<1, BMAX>>>();
    scatter_kernel<<<NB, 256>>>(batch, n, B);
    main_kernel<<<B * CPG, 256, MAIN_SMEM>>>(s, b1, b2, out, B);
}

// round 11
// speedup vs baseline: 1.1743x; 1.1743x over previous
#include <cuda_runtime.h>

#define KC 32
#define LC 64
#define HC 256
#define OC 32
#define BMAX 256
#define NMAX 100000
#define NB 128            // histogram / scatter blocks
#define CPG 4             // CTAs per graph
#define TN 8              // nodes per warp
#define CHUNK 64          // nodes per CTA chunk
#define HSTR 260          // padded h row stride (floats)

#define ZW1_SMEM ((LC*HC + 4*LC) * 4)
#define MAIN_FLOATS (KC*HC + HC*OC + CHUNK*KC + 8*4*HSTR)
#define MAIN_SMEM (MAIN_FLOATS*4 + CHUNK*4)

typedef unsigned long long u64;

__device__ __forceinline__ u64 fma2(u64 a, u64 b, u64 c) {
    u64 d;
    asm("fma.rn.f32x2 %0, %1, %2, %3;" : "=l"(d) : "l"(a), "l"(b), "l"(c));
    return d;
}
__device__ __forceinline__ u64 pack2(float lo, float hi) {
    u64 d;
    asm("mov.b64 %0, {%1, %2};" : "=l"(d) : "f"(lo), "f"(hi));
    return d;
}
__device__ __forceinline__ void unpack2(u64 v, float& lo, float& hi) {
    asm("mov.b64 {%0, %1}, %2;" : "=f"(lo), "=f"(hi) : "l"(v));
}

// ---------------- device scratch ------------------------------------------
__device__ float g_zw1[BMAX * KC * HC];    // 8 MB: z @ W1
__device__ float g_w2e[HC * OC];           // W2 repacked [jp2][jj][og][4]
__device__ int   g_perm[NMAX];
__device__ int   g_hist[BMAX];
__device__ int   g_cnt[BMAX];
__device__ int   g_binstart[BMAX];
__device__ int   g_cursor[BMAX];
__device__ int   g_bh[NB * BMAX];          // per-block histograms

// ---------------- 1. prep: zW1 GEMM | W2 repack | per-block hist ----------
__global__ void prep_kernel(const float* __restrict__ z,
                            const float* __restrict__ W1,
                            const float* __restrict__ W2,
                            const int* __restrict__ batch,
                            int n, int B, int zb) {
    int tid = threadIdx.x;
    int bx = blockIdx.x;

    if (bx >= zb + 8) {
        // ---- per-block histogram + global histogram ----
        __shared__ int sh[BMAX];
        int blk = bx - zb - 8;
        sh[tid] = 0;
        __syncthreads();
        int span = (n + NB - 1) / NB;
        int lo = blk * span, hi = min(n, lo + span);
        for (int i = lo + tid; i < hi; i += 256) {
            int b = batch[i];
            if (b >= 0 && b < B) atomicAdd(&sh[b], 1);
        }
        __syncthreads();
        g_bh[blk * BMAX + tid] = sh[tid];
        if (sh[tid]) atomicAdd(&g_hist[tid], sh[tid]);
        return;
    }
    if (bx >= zb) {
        // ---- W2 repack: float4 idx -> [jp2][jj][og][4] ----
        int idx = (bx - zb) * 256 + tid;     // 0..2047
        int jp2 = idx >> 5;
        int rem = idx & 31;
        int jj = rem >> 3, og = rem & 7;
        int j = jp2 * 4 + jj, o0 = og * 4;
        float4 v;
        v.x = W2[j * OC + o0 + 0];
        v.y = W2[j * OC + o0 + 1];
        v.z = W2[j * OC + o0 + 2];
        v.w = W2[j * OC + o0 + 3];
        ((float4*)g_w2e)[idx] = v;
        return;
    }
    // ---- zW1 = z @ W1 ----
    extern __shared__ __align__(16) float sm[];
    float* w1s = sm;              // LC*HC
    float* zs  = sm + LC * HC;    // 4*LC

    for (int i = tid; i < (LC * HC) / 4; i += 256)
        ((float4*)w1s)[i] = ((const float4*)W1)[i];

    int rows = zb * 16;           // == B*KC
    int row0 = bx * 16;
    for (int g = 0; g < 4; g++) {
        int rbase = row0 + g * 16 / 4;        // row0 + g*4
        rbase = row0 + g * 4;
        __syncthreads();
        int rr = tid >> 6, ll = tid & 63;
        if (rbase + rr < rows)
            zs[rr * LC + ll] = z[(size_t)(rbase + rr) * LC + ll];
        __syncthreads();

        float a0 = 0.f, a1 = 0.f, a2 = 0.f, a3 = 0.f;
        #pragma unroll
        for (int l = 0; l < LC; l++) {
            float w = w1s[l * HC + tid];
            a0 += zs[0 * LC + l] * w;
            a1 += zs[1 * LC + l] * w;
            a2 += zs[2 * LC + l] * w;
            a3 += zs[3 * LC + l] * w;
        }
        if (rbase + 3 < rows) {
            g_zw1[(size_t)(rbase + 0) * HC + tid] = a0;
            g_zw1[(size_t)(rbase + 1) * HC + tid] = a1;
            g_zw1[(size_t)(rbase + 2) * HC + tid] = a2;
            g_zw1[(size_t)(rbase + 3) * HC + tid] = a3;
        }
    }
}

// ---------------- 2. scan: binstart + cnt + cursor init, re-zero hist -----
__global__ void scan_kernel() {
    __shared__ int tmp[BMAX];
    int tid = threadIdx.x;
    int v0 = g_hist[tid];
    g_cnt[tid]  = v0;
    g_hist[tid] = 0;               // idempotent across graph replays
    tmp[tid] = v0;
    __syncthreads();
    for (int d = 1; d < BMAX; d <<= 1) {
        int v = (tid >= d) ? tmp[tid - d] : 0;
        __syncthreads();
        tmp[tid] += v;
        __syncthreads();
    }
    int start = tmp[tid] - v0;
    g_binstart[tid] = start;
    g_cursor[tid]   = start;
}

// ---------------- 3. scatter: block reserves ranges, smem cursors ---------
__global__ void scatter_kernel(const int* __restrict__ batch, int n, int B) {
    __shared__ int cur[BMAX];
    int tid = threadIdx.x, blk = blockIdx.x;
    int mine = g_bh[blk * BMAX + tid];
    cur[tid] = mine ? atomicAdd(&g_cursor[tid], mine) : 0;   // spread atomics
    __syncthreads();
    int span = (n + NB - 1) / NB;
    int lo = blk * span, hi = min(n, lo + span);
    for (int i = lo + tid; i < hi; i += 256) {
        int b = batch[i];
        if (b < 0 || b >= B) continue;
        int pos = atomicAdd(&cur[b], 1);    // smem atomic
        g_perm[pos] = i;
    }
}

// ---------------- 4. main fused kernel ------------------------------------
__global__ __launch_bounds__(256, 2)
void main_kernel(const float* __restrict__ s,
                 const float* __restrict__ b1, const float* __restrict__ b2,
                 float* __restrict__ out, int B) {
    extern __shared__ __align__(16) float sm[];
    float* zw1s = sm;                      // 8192
    float* w2e  = zw1s + KC * HC;          // 8192
    float* ss   = w2e + HC * OC;           // 2048
    float* hsm  = ss + CHUNK * KC;         // 8*4*HSTR = 8320
    int*   nids = (int*)(hsm + 8 * 4 * HSTR);

    int tid = threadIdx.x;
    int b   = blockIdx.x % B;
    int c0  = blockIdx.x / B;
    int cnt = g_cnt[b];
    if (c0 * CHUNK >= cnt) return;
    int start = g_binstart[b];

    // prologue: linear float4 copies of per-graph zW1 + repacked W2
    const float4* zw1g = (const float4*)(g_zw1 + (size_t)b * KC * HC);
    #pragma unroll
    for (int i = 0; i < 8; i++)
        ((float4*)zw1s)[tid + i * 256] = zw1g[tid + i * 256];
    #pragma unroll
    for (int i = 0; i < 8; i++)
        ((float4*)w2e)[tid + i * 256] = ((const float4*)g_w2e)[tid + i * 256];

    int w = tid >> 5, lane = tid & 31;
    int tp = lane >> 3, og = lane & 7;     // out-stage role
    float* hw = hsm + w * (4 * HSTR);

    u64 bp[4];
    {
        ulonglong2 p0 = *(const ulonglong2*)&b1[lane * 8];
        ulonglong2 p1 = *(const ulonglong2*)&b1[lane * 8 + 4];
        bp[0] = p0.x; bp[1] = p0.y; bp[2] = p1.x; bp[3] = p1.y;
    }
    float4 b2v = *(const float4*)&b2[og * 4];

    for (int c = c0; c * CHUNK < cnt; c += CPG) {
        int nbase = c * CHUNK;
        __syncthreads();
        // stage nids + s rows: 512 float4, 2 per thread
        #pragma unroll
        for (int e = 0; e < 2; e++) {
            int idx = e * 256 + tid;
            int i = idx >> 3, q = idx & 7;
            int gi = nbase + i;
            int nid = (gi < cnt) ? g_perm[start + gi] : -1;
            if (q == 0) nids[i] = nid;
            float4 v = make_float4(0.f, 0.f, 0.f, 0.f);
            if (nid >= 0) v = ((const float4*)(s + (size_t)nid * KC))[q];
            ((float4*)(ss + i * KC))[q] = v;
        }
        __syncthreads();

        // ---- h-stage: lane owns j = lane*8..+7 ; 8 nodes per warp
        u64 ha[TN][4];
        #pragma unroll
        for (int t = 0; t < TN; t++) {
            ha[t][0] = bp[0]; ha[t][1] = bp[1];
            ha[t][2] = bp[2]; ha[t][3] = bp[3];
        }
        const float* ssw = ss + w * TN * KC;
        #pragma unroll 2
        for (int kg = 0; kg < KC / 4; kg++) {
            // one float4 broadcast per node covers 4 k's
            float4 s4[TN];
            #pragma unroll
            for (int t = 0; t < TN; t++)
                s4[t] = ((const float4*)(ssw + t * KC))[kg];
            #pragma unroll
            for (int kk = 0; kk < 4; kk++) {
                int k = kg * 4 + kk;
                ulonglong2 wa = *(const ulonglong2*)&zw1s[k * HC + lane * 8];
                ulonglong2 wb = *(const ulonglong2*)&zw1s[k * HC + lane * 8 + 4];
                #pragma unroll
                for (int t = 0; t < TN; t++) {
                    const float* sp = (const float*)&s4[t];
                    float sv = sp[kk];
                    u64 svp = pack2(sv, sv);
                    ha[t][0] = fma2(svp, wa.x, ha[t][0]);
                    ha[t][1] = fma2(svp, wa.y, ha[t][1]);
                    ha[t][2] = fma2(svp, wb.x, ha[t][2]);
                    ha[t][3] = fma2(svp, wb.y, ha[t][3]);
                }
            }
        }

        // ---- out-stage: two passes of 4 nodes
        #pragma unroll
        for (int p = 0; p < 2; p++) {
            #pragma unroll
            for (int t = 0; t < 4; t++) {
                int tt = p * 4 + t;
                float x, y;
                float4 v0, v1;
                unpack2(ha[tt][0], x, y); v0.x = fmaxf(x,0.f); v0.y = fmaxf(y,0.f);
                unpack2(ha[tt][1], x, y); v0.z = fmaxf(x,0.f); v0.w = fmaxf(y,0.f);
                unpack2(ha[tt][2], x, y); v1.x = fmaxf(x,0.f); v1.y = fmaxf(y,0.f);
                unpack2(ha[tt][3], x, y); v1.z = fmaxf(x,0.f); v1.w = fmaxf(y,0.f);
                float* dst = hw + t * HSTR + lane * 8;
                *(float4*)(dst)     = v0;
                *(float4*)(dst + 4) = v1;
            }
            __syncwarp();

            u64 acc0 = 0ull, acc1 = 0ull;
            const float* hrow = hw + tp * HSTR;
            #pragma unroll 4
            for (int jp2 = 0; jp2 < HC / 4; jp2++) {
                float4 hv = *(const float4*)&hrow[jp2 * 4];
                const float* wb4 = w2e + jp2 * 128 + og * 4;
                ulonglong2 w0 = *(const ulonglong2*)&wb4[0];
                ulonglong2 w1 = *(const ulonglong2*)&wb4[32];
                ulonglong2 w2 = *(const ulonglong2*)&wb4[64];
                ulonglong2 w3 = *(const ulonglong2*)&wb4[96];
                u64 h0 = pack2(hv.x, hv.x), h1 = pack2(hv.y, hv.y);
                u64 h2 = pack2(hv.z, hv.z), h3 = pack2(hv.w, hv.w);
                acc0 = fma2(h0, w0.x, acc0); acc1 = fma2(h0, w0.y, acc1);
                acc0 = fma2(h1, w1.x, acc0); acc1 = fma2(h1, w1.y, acc1);
                acc0 = fma2(h2, w2.x, acc0); acc1 = fma2(h2, w2.y, acc1);
                acc0 = fma2(h3, w3.x, acc0); acc1 = fma2(h3, w3.y, acc1);
            }
            int nid = nids[w * TN + p * 4 + tp];
            if (nid >= 0) {
                float4 r;
                unpack2(acc0, r.x, r.y);
                unpack2(acc1, r.z, r.w);
                r.x += b2v.x; r.y += b2v.y; r.z += b2v.z; r.w += b2v.w;
                *(float4*)(out + (size_t)nid * OC + og * 4) = r;
            }
            __syncwarp();
        }
    }
}

// ---------------- launch ---------------------------------------------------
extern "C" void kernel_launch(void* const* d_in, const int* in_sizes, int n_in,
                              void* d_out, int out_size) {
    const float* z     = (const float*)d_in[0];
    const float* s     = (const float*)d_in[1];
    const int*   batch = (const int*)d_in[2];   // JAX x64 disabled -> int32
    const float* W1    = (const float*)d_in[3];
    const float* b1    = (const float*)d_in[4];
    const float* W2    = (const float*)d_in[5];
    const float* b2    = (const float*)d_in[6];
    float*       out   = (float*)d_out;

    int n = in_sizes[2];
    int B = in_sizes[0] / (KC * LC);
    int zb = (B * KC + 15) / 16;

    cudaFuncSetAttribute(prep_kernel,
        cudaFuncAttributeMaxDynamicSharedMemorySize, ZW1_SMEM);
    cudaFuncSetAttribute(main_kernel,
        cudaFuncAttributeMaxDynamicSharedMemorySize, MAIN_SMEM);

    prep_kernel<<<zb + 8 + NB, 256, ZW1_SMEM>>>(z, W1, W2, batch, n, B, zb);
    scan_kernel<<<1, BMAX>>>();
    scatter_kernel<<<NB, 256>>>(batch, n, B);
    main_kernel<<<B * CPG, 256, MAIN_SMEM>>>(s, b1, b2, out, B);
}

// round 12
// speedup vs baseline: 1.1777x; 1.0029x over previous
#include <cuda_runtime.h>

#define KC 32
#define LC 64
#define HC 256
#define OC 32
#define BMAX 256
#define NMAX 100000
#define NB 128            // histogram / scatter blocks
#define CPG 4             // CTAs per graph
#define TN 8              // nodes per warp
#define CHUNK 64          // nodes per CTA chunk
#define HSTR 260          // padded h row stride (floats)

#define ZW1_SMEM ((LC*HC + 4*LC) * 4)
#define MAIN_FLOATS (KC*HC + HC*OC + CHUNK*KC + 8*4*HSTR)
#define MAIN_SMEM (MAIN_FLOATS*4 + CHUNK*4)

typedef unsigned long long u64;

__device__ __forceinline__ u64 fma2(u64 a, u64 b, u64 c) {
    u64 d;
    asm("fma.rn.f32x2 %0, %1, %2, %3;" : "=l"(d) : "l"(a), "l"(b), "l"(c));
    return d;
}
__device__ __forceinline__ u64 pack2(float lo, float hi) {
    u64 d;
    asm("mov.b64 %0, {%1, %2};" : "=l"(d) : "f"(lo), "f"(hi));
    return d;
}
__device__ __forceinline__ void unpack2(u64 v, float& lo, float& hi) {
    asm("mov.b64 {%0, %1}, %2;" : "=f"(lo), "=f"(hi) : "l"(v));
}

// ---------------- device scratch ------------------------------------------
__device__ float g_zw1[BMAX * KC * HC];    // 8 MB: z @ W1
__device__ float g_w2e[HC * OC];           // W2 repacked [jp2][jj][og][4]
__device__ int   g_perm[NMAX];
__device__ int   g_hist[BMAX];
__device__ int   g_cnt[BMAX];
__device__ int   g_binstart[BMAX];
__device__ int   g_cursor[BMAX];
__device__ int   g_bh[NB * BMAX];          // per-block histograms

// ---------------- 1. prep: zW1 GEMM | W2 repack | per-block hist ----------
__global__ void prep_kernel(const float* __restrict__ z,
                            const float* __restrict__ W1,
                            const float* __restrict__ W2,
                            const int* __restrict__ batch,
                            int n, int B, int zb) {
    int tid = threadIdx.x;
    int bx = blockIdx.x;

    if (bx >= zb + 8) {
        // ---- per-block histogram + global histogram ----
        __shared__ int sh[BMAX];
        int blk = bx - zb - 8;
        sh[tid] = 0;
        __syncthreads();
        int span = (n + NB - 1) / NB;
        int lo = blk * span, hi = min(n, lo + span);
        for (int i = lo + tid; i < hi; i += 256) {
            int b = batch[i];
            if (b >= 0 && b < B) atomicAdd(&sh[b], 1);
        }
        __syncthreads();
        g_bh[blk * BMAX + tid] = sh[tid];
        if (sh[tid]) atomicAdd(&g_hist[tid], sh[tid]);
        return;
    }
    if (bx >= zb) {
        // ---- W2 repack: float4 idx -> [jp2][jj][og][4] ----
        int idx = (bx - zb) * 256 + tid;     // 0..2047
        int jp2 = idx >> 5;
        int rem = idx & 31;
        int jj = rem >> 3, og = rem & 7;
        int j = jp2 * 4 + jj, o0 = og * 4;
        float4 v;
        v.x = W2[j * OC + o0 + 0];
        v.y = W2[j * OC + o0 + 1];
        v.z = W2[j * OC + o0 + 2];
        v.w = W2[j * OC + o0 + 3];
        ((float4*)g_w2e)[idx] = v;
        return;
    }
    // ---- zW1 = z @ W1 ----
    extern __shared__ __align__(16) float sm[];
    float* w1s = sm;              // LC*HC
    float* zs  = sm + LC * HC;    // 4*LC

    for (int i = tid; i < (LC * HC) / 4; i += 256)
        ((float4*)w1s)[i] = ((const float4*)W1)[i];

    int rows = zb * 16;           // == B*KC
    int row0 = bx * 16;
    for (int g = 0; g < 4; g++) {
        int rbase = row0 + g * 16 / 4;        // row0 + g*4
        rbase = row0 + g * 4;
        __syncthreads();
        int rr = tid >> 6, ll = tid & 63;
        if (rbase + rr < rows)
            zs[rr * LC + ll] = z[(size_t)(rbase + rr) * LC + ll];
        __syncthreads();

        float a0 = 0.f, a1 = 0.f, a2 = 0.f, a3 = 0.f;
        #pragma unroll
        for (int l = 0; l < LC; l++) {
            float w = w1s[l * HC + tid];
            a0 += zs[0 * LC + l] * w;
            a1 += zs[1 * LC + l] * w;
            a2 += zs[2 * LC + l] * w;
            a3 += zs[3 * LC + l] * w;
        }
        if (rbase + 3 < rows) {
            g_zw1[(size_t)(rbase + 0) * HC + tid] = a0;
            g_zw1[(size_t)(rbase + 1) * HC + tid] = a1;
            g_zw1[(size_t)(rbase + 2) * HC + tid] = a2;
            g_zw1[(size_t)(rbase + 3) * HC + tid] = a3;
        }
    }
}

// ---------------- 2. scan: binstart + cnt + cursor init, re-zero hist -----
__global__ void scan_kernel() {
    __shared__ int tmp[BMAX];
    int tid = threadIdx.x;
    int v0 = g_hist[tid];
    g_cnt[tid]  = v0;
    g_hist[tid] = 0;               // idempotent across graph replays
    tmp[tid] = v0;
    __syncthreads();
    for (int d = 1; d < BMAX; d <<= 1) {
        int v = (tid >= d) ? tmp[tid - d] : 0;
        __syncthreads();
        tmp[tid] += v;
        __syncthreads();
    }
    int start = tmp[tid] - v0;
    g_binstart[tid] = start;
    g_cursor[tid]   = start;
}

// ---------------- 3. scatter: block reserves ranges, smem cursors ---------
__global__ void scatter_kernel(const int* __restrict__ batch, int n, int B) {
    __shared__ int cur[BMAX];
    int tid = threadIdx.x, blk = blockIdx.x;
    int mine = g_bh[blk * BMAX + tid];
    cur[tid] = mine ? atomicAdd(&g_cursor[tid], mine) : 0;   // spread atomics
    __syncthreads();
    int span = (n + NB - 1) / NB;
    int lo = blk * span, hi = min(n, lo + span);
    for (int i = lo + tid; i < hi; i += 256) {
        int b = batch[i];
        if (b < 0 || b >= B) continue;
        int pos = atomicAdd(&cur[b], 1);    // smem atomic
        g_perm[pos] = i;
    }
}

// ---------------- 4. main fused kernel ------------------------------------
__global__ __launch_bounds__(256, 2)
void main_kernel(const float* __restrict__ s,
                 const float* __restrict__ b1, const float* __restrict__ b2,
                 float* __restrict__ out, int B) {
    extern __shared__ __align__(16) float sm[];
    float* zw1s = sm;                      // 8192
    float* w2e  = zw1s + KC * HC;          // 8192
    float* ss   = w2e + HC * OC;           // 2048
    float* hsm  = ss + CHUNK * KC;         // 8*4*HSTR = 8320
    int*   nids = (int*)(hsm + 8 * 4 * HSTR);

    int tid = threadIdx.x;
    int b   = blockIdx.x % B;
    int c0  = blockIdx.x / B;
    int cnt = g_cnt[b];
    if (c0 * CHUNK >= cnt) return;
    int start = g_binstart[b];

    // prologue: linear float4 copies of per-graph zW1 + repacked W2
    const float4* zw1g = (const float4*)(g_zw1 + (size_t)b * KC * HC);
    #pragma unroll
    for (int i = 0; i < 8; i++)
        ((float4*)zw1s)[tid + i * 256] = zw1g[tid + i * 256];
    #pragma unroll
    for (int i = 0; i < 8; i++)
        ((float4*)w2e)[tid + i * 256] = ((const float4*)g_w2e)[tid + i * 256];

    int w = tid >> 5, lane = tid & 31;
    int tp = lane >> 3, og = lane & 7;     // out-stage role
    float* hw = hsm + w * (4 * HSTR);

    u64 bp[4];
    {
        ulonglong2 p0 = *(const ulonglong2*)&b1[lane * 8];
        ulonglong2 p1 = *(const ulonglong2*)&b1[lane * 8 + 4];
        bp[0] = p0.x; bp[1] = p0.y; bp[2] = p1.x; bp[3] = p1.y;
    }
    float4 b2v = *(const float4*)&b2[og * 4];

    for (int c = c0; c * CHUNK < cnt; c += CPG) {
        int nbase = c * CHUNK;
        __syncthreads();
        // stage nids + s rows: 512 float4, 2 per thread
        #pragma unroll
        for (int e = 0; e < 2; e++) {
            int idx = e * 256 + tid;
            int i = idx >> 3, q = idx & 7;
            int gi = nbase + i;
            int nid = (gi < cnt) ? g_perm[start + gi] : -1;
            if (q == 0) nids[i] = nid;
            float4 v = make_float4(0.f, 0.f, 0.f, 0.f);
            if (nid >= 0) v = ((const float4*)(s + (size_t)nid * KC))[q];
            ((float4*)(ss + i * KC))[q] = v;
        }
        __syncthreads();

        // ---- h-stage: lane owns j = lane*8..+7 ; 8 nodes per warp
        u64 ha[TN][4];
        #pragma unroll
        for (int t = 0; t < TN; t++) {
            ha[t][0] = bp[0]; ha[t][1] = bp[1];
            ha[t][2] = bp[2]; ha[t][3] = bp[3];
        }
        const float* ssw = ss + w * TN * KC;
        #pragma unroll 2
        for (int kg = 0; kg < KC / 4; kg++) {
            // one float4 broadcast per node covers 4 k's
            float4 s4[TN];
            #pragma unroll
            for (int t = 0; t < TN; t++)
                s4[t] = ((const float4*)(ssw + t * KC))[kg];
            #pragma unroll
            for (int kk = 0; kk < 4; kk++) {
                int k = kg * 4 + kk;
                ulonglong2 wa = *(const ulonglong2*)&zw1s[k * HC + lane * 8];
                ulonglong2 wb = *(const ulonglong2*)&zw1s[k * HC + lane * 8 + 4];
                #pragma unroll
                for (int t = 0; t < TN; t++) {
                    const float* sp = (const float*)&s4[t];
                    float sv = sp[kk];
                    u64 svp = pack2(sv, sv);
                    ha[t][0] = fma2(svp, wa.x, ha[t][0]);
                    ha[t][1] = fma2(svp, wa.y, ha[t][1]);
                    ha[t][2] = fma2(svp, wb.x, ha[t][2]);
                    ha[t][3] = fma2(svp, wb.y, ha[t][3]);
                }
            }
        }

        // ---- out-stage: two passes of 4 nodes
        #pragma unroll
        for (int p = 0; p < 2; p++) {
            #pragma unroll
            for (int t = 0; t < 4; t++) {
                int tt = p * 4 + t;
                float x, y;
                float4 v0, v1;
                unpack2(ha[tt][0], x, y); v0.x = fmaxf(x,0.f); v0.y = fmaxf(y,0.f);
                unpack2(ha[tt][1], x, y); v0.z = fmaxf(x,0.f); v0.w = fmaxf(y,0.f);
                unpack2(ha[tt][2], x, y); v1.x = fmaxf(x,0.f); v1.y = fmaxf(y,0.f);
                unpack2(ha[tt][3], x, y); v1.z = fmaxf(x,0.f); v1.w = fmaxf(y,0.f);
                float* dst = hw + t * HSTR + lane * 8;
                *(float4*)(dst)     = v0;
                *(float4*)(dst + 4) = v1;
            }
            __syncwarp();

            u64 acc0 = 0ull, acc1 = 0ull;
            const float* hrow = hw + tp * HSTR;
            #pragma unroll 4
            for (int jp2 = 0; jp2 < HC / 4; jp2++) {
                float4 hv = *(const float4*)&hrow[jp2 * 4];
                const float* wb4 = w2e + jp2 * 128 + og * 4;
                ulonglong2 w0 = *(const ulonglong2*)&wb4[0];
                ulonglong2 w1 = *(const ulonglong2*)&wb4[32];
                ulonglong2 w2 = *(const ulonglong2*)&wb4[64];
                ulonglong2 w3 = *(const ulonglong2*)&wb4[96];
                u64 h0 = pack2(hv.x, hv.x), h1 = pack2(hv.y, hv.y);
                u64 h2 = pack2(hv.z, hv.z), h3 = pack2(hv.w, hv.w);
                acc0 = fma2(h0, w0.x, acc0); acc1 = fma2(h0, w0.y, acc1);
                acc0 = fma2(h1, w1.x, acc0); acc1 = fma2(h1, w1.y, acc1);
                acc0 = fma2(h2, w2.x, acc0); acc1 = fma2(h2, w2.y, acc1);
                acc0 = fma2(h3, w3.x, acc0); acc1 = fma2(h3, w3.y, acc1);
            }
            int nid = nids[w * TN + p * 4 + tp];
            if (nid >= 0) {
                float4 r;
                unpack2(acc0, r.x, r.y);
                unpack2(acc1, r.z, r.w);
                r.x += b2v.x; r.y += b2v.y; r.z += b2v.z; r.w += b2v.w;
                *(float4*)(out + (size_t)nid * OC + og * 4) = r;
            }
            __syncwarp();
        }
    }
}

// ---------------- launch ---------------------------------------------------
extern "C" void kernel_launch(void* const* d_in, const int* in_sizes, int n_in,
                              void* d_out, int out_size) {
    const float* z     = (const float*)d_in[0];
    const float* s     = (const float*)d_in[1];
    const int*   batch = (const int*)d_in[2];   // JAX x64 disabled -> int32
    const float* W1    = (const float*)d_in[3];
    const float* b1    = (const float*)d_in[4];
    const float* W2    = (const float*)d_in[5];
    const float* b2    = (const float*)d_in[6];
    float*       out   = (float*)d_out;

    int n = in_sizes[2];
    int B = in_sizes[0] / (KC * LC);
    int zb = (B * KC + 15) / 16;

    cudaFuncSetAttribute(prep_kernel,
        cudaFuncAttributeMaxDynamicSharedMemorySize, ZW1_SMEM);
    cudaFuncSetAttribute(main_kernel,
        cudaFuncAttributeMaxDynamicSharedMemorySize, MAIN_SMEM);

    prep_kernel<<<zb + 8 + NB, 256, ZW1_SMEM>>>(z, W1, W2, batch, n, B, zb);
    scan_kernel<<<1, BMAX>>>();
    scatter_kernel<<<NB, 256>>>(batch, n, B);
    main_kernel<<<B * CPG, 256, MAIN_SMEM>>>(s, b1, b2, out, B);
}

// round 13
// speedup vs baseline: 1.8394x; 1.5618x over previous
#include <cuda_runtime.h>

#define KC 32
#define LC 64
#define HC 256
#define OC 32
#define BMAX 256
#define NMAX 100000
#define NB 128            // histogram / scatter blocks
#define CPG 4             // CTAs per graph
#define CHUNK 64          // nodes per CTA chunk
#define SS 36             // ss row stride (floats)
#define HS 264            // hbuf row stride (floats)
#define PS 36             // pbuf row stride (floats)

#define ZW1_SMEM ((LC*HC + 4*LC) * 4)
#define MAIN_FLOATS (KC*HC + HC*OC + CHUNK*SS + CHUNK*HS + 4*CHUNK*PS)
#define MAIN_SMEM (MAIN_FLOATS*4 + CHUNK*4)

typedef unsigned long long u64;

__device__ __forceinline__ u64 fma2(u64 a, u64 b, u64 c) {
    u64 d;
    asm("fma.rn.f32x2 %0, %1, %2, %3;" : "=l"(d) : "l"(a), "l"(b), "l"(c));
    return d;
}
__device__ __forceinline__ u64 pack2(float lo, float hi) {
    u64 d;
    asm("mov.b64 %0, {%1, %2};" : "=l"(d) : "f"(lo), "f"(hi));
    return d;
}
__device__ __forceinline__ void unpack2(u64 v, float& lo, float& hi) {
    asm("mov.b64 {%0, %1}, %2;" : "=f"(lo), "=f"(hi) : "l"(v));
}

// ---------------- device scratch ------------------------------------------
__device__ float g_zw1[BMAX * KC * HC];    // 8 MB: z @ W1
__device__ int   g_perm[NMAX];
__device__ int   g_hist[BMAX];
__device__ int   g_cnt[BMAX];
__device__ int   g_binstart[BMAX];
__device__ int   g_cursor[BMAX];
__device__ int   g_bh[NB * BMAX];          // per-block histograms

// ---------------- 1. prep: zW1 GEMM | per-block hist -----------------------
__global__ void prep_kernel(const float* __restrict__ z,
                            const float* __restrict__ W1,
                            const int* __restrict__ batch,
                            int n, int B, int zb) {
    int tid = threadIdx.x;
    int bx = blockIdx.x;

    if (bx >= zb) {
        __shared__ int sh[BMAX];
        int blk = bx - zb;
        sh[tid] = 0;
        __syncthreads();
        int span = (n + NB - 1) / NB;
        int lo = blk * span, hi = min(n, lo + span);
        for (int i = lo + tid; i < hi; i += 256) {
            int b = batch[i];
            if (b >= 0 && b < B) atomicAdd(&sh[b], 1);
        }
        __syncthreads();
        g_bh[blk * BMAX + tid] = sh[tid];
        if (sh[tid]) atomicAdd(&g_hist[tid], sh[tid]);
        return;
    }
    extern __shared__ __align__(16) float sm[];
    float* w1s = sm;              // LC*HC
    float* zs  = sm + LC * HC;    // 4*LC

    for (int i = tid; i < (LC * HC) / 4; i += 256)
        ((float4*)w1s)[i] = ((const float4*)W1)[i];

    int rows = zb * 16;
    int row0 = bx * 16;
    for (int g = 0; g < 4; g++) {
        int rbase = row0 + g * 4;
        __syncthreads();
        int rr = tid >> 6, ll = tid & 63;
        if (rbase + rr < rows)
            zs[rr * LC + ll] = z[(size_t)(rbase + rr) * LC + ll];
        __syncthreads();

        float a0 = 0.f, a1 = 0.f, a2 = 0.f, a3 = 0.f;
        #pragma unroll
        for (int l = 0; l < LC; l++) {
            float w = w1s[l * HC + tid];
            a0 += zs[0 * LC + l] * w;
            a1 += zs[1 * LC + l] * w;
            a2 += zs[2 * LC + l] * w;
            a3 += zs[3 * LC + l] * w;
        }
        if (rbase + 3 < rows) {
            g_zw1[(size_t)(rbase + 0) * HC + tid] = a0;
            g_zw1[(size_t)(rbase + 1) * HC + tid] = a1;
            g_zw1[(size_t)(rbase + 2) * HC + tid] = a2;
            g_zw1[(size_t)(rbase + 3) * HC + tid] = a3;
        }
    }
}

// ---------------- 2. scan ---------------------------------------------------
__global__ void scan_kernel() {
    __shared__ int tmp[BMAX];
    int tid = threadIdx.x;
    int v0 = g_hist[tid];
    g_cnt[tid]  = v0;
    g_hist[tid] = 0;               // idempotent across graph replays
    tmp[tid] = v0;
    __syncthreads();
    for (int d = 1; d < BMAX; d <<= 1) {
        int v = (tid >= d) ? tmp[tid - d] : 0;
        __syncthreads();
        tmp[tid] += v;
        __syncthreads();
    }
    int start = tmp[tid] - v0;
    g_binstart[tid] = start;
    g_cursor[tid]   = start;
}

// ---------------- 3. scatter ------------------------------------------------
__global__ void scatter_kernel(const int* __restrict__ batch, int n, int B) {
    __shared__ int cur[BMAX];
    int tid = threadIdx.x, blk = blockIdx.x;
    int mine = g_bh[blk * BMAX + tid];
    cur[tid] = mine ? atomicAdd(&g_cursor[tid], mine) : 0;   // spread atomics
    __syncthreads();
    int span = (n + NB - 1) / NB;
    int lo = blk * span, hi = min(n, lo + span);
    for (int i = lo + tid; i < hi; i += 256) {
        int b = batch[i];
        if (b < 0 || b >= B) continue;
        int pos = atomicAdd(&cur[b], 1);    // smem atomic
        g_perm[pos] = i;
    }
}

// ---------------- 4. main fused kernel --------------------------------------
// H   phase: warp(nh, jw): 32 nodes x 64 j.  lane(ng, jg): 8n x 8j (split octet
//            j0=jw*64+jg*4 and j1=j0+32); node = nh*32 + 4t + ng (strided).
// OUT phase: warp(nh, q=j-quarter): 32n x 32o x 64j partial. lane(ng, og=jg):
//            8n x 4o.  Partials reduced over 4 quarters via pbuf.
__global__ __launch_bounds__(256, 1)
void main_kernel(const float* __restrict__ s, const float* __restrict__ W2,
                 const float* __restrict__ b1, const float* __restrict__ b2,
                 float* __restrict__ out, int B) {
    extern __shared__ __align__(16) float sm[];
    float* zw1s = sm;                        // [k][j]  32x256 = 8192
    float* w2s  = zw1s + KC * HC;            // [j][o] 256x32  = 8192
    float* ss   = w2s + HC * OC;             // [n][SS]        = 2304
    float* hbuf = ss + CHUNK * SS;           // [n][HS]        = 16896
    float* pbuf = hbuf + CHUNK * HS;         // [q][n][PS]     = 9216
    int*   nids = (int*)(pbuf + 4 * CHUNK * PS);

    int tid = threadIdx.x;
    int b   = blockIdx.x % B;
    int c0  = blockIdx.x / B;
    int cnt = g_cnt[b];
    if (c0 * CHUNK >= cnt) return;
    int start = g_binstart[b];

    // prologue: stage per-graph zW1 and W2 (both straight copies)
    const float4* zw1g = (const float4*)(g_zw1 + (size_t)b * KC * HC);
    #pragma unroll
    for (int i = 0; i < 8; i++)
        ((float4*)zw1s)[tid + i * 256] = zw1g[tid + i * 256];
    #pragma unroll
    for (int i = 0; i < 8; i++)
        ((float4*)w2s)[tid + i * 256] = ((const float4*)W2)[tid + i * 256];

    int w = tid >> 5, lane = tid & 31;
    int nh = w & 1;                  // node half (both phases)
    int jw = w >> 1;                 // H: j-group   OUT: j-quarter q
    int ng = lane >> 3;              // node sub-group
    int jg = lane & 7;               // H: j sub     OUT: o-quad
    int j0 = jw * 64 + jg * 4;
    int j1 = j0 + 32;
    int nrow0 = nh * 32 + ng;        // node = nrow0 + 4*t

    // b1 bias quads in registers (packed)
    u64 bq[4];
    {
        float4 v = *(const float4*)&b1[j0];
        bq[0] = pack2(v.x, v.y); bq[1] = pack2(v.z, v.w);
        v = *(const float4*)&b1[j1];
        bq[2] = pack2(v.x, v.y); bq[3] = pack2(v.z, v.w);
    }

    for (int c = c0; c * CHUNK < cnt; c += CPG) {
        int nbase = c * CHUNK;
        __syncthreads();             // protects ss/nids/hbuf/pbuf reuse (+prologue)
        // stage nids + s rows (512 float4, 2 per thread)
        #pragma unroll
        for (int e = 0; e < 2; e++) {
            int idx = e * 256 + tid;
            int i = idx >> 3, qq = idx & 7;
            int gi = nbase + i;
            int nid = (gi < cnt) ? g_perm[start + gi] : -1;
            if (qq == 0) nids[i] = nid;
            float4 v = make_float4(0.f, 0.f, 0.f, 0.f);
            if (nid >= 0) v = ((const float4*)(s + (size_t)nid * KC))[qq];
            *(float4*)&ss[i * SS + qq * 4] = v;
        }
        __syncthreads();

        // ================= H phase =================
        u64 ha[8][4];
        #pragma unroll
        for (int t = 0; t < 8; t++) {
            ha[t][0] = bq[0]; ha[t][1] = bq[1];
            ha[t][2] = bq[2]; ha[t][3] = bq[3];
        }
        #pragma unroll
        for (int kg = 0; kg < 8; kg++) {
            float4 s4[8];
            #pragma unroll
            for (int t = 0; t < 8; t++)
                s4[t] = *(const float4*)&ss[(nrow0 + 4 * t) * SS + kg * 4];
            #pragma unroll
            for (int kk = 0; kk < 4; kk++) {
                int k = kg * 4 + kk;
                ulonglong2 wa = *(const ulonglong2*)&zw1s[k * HC + j0];
                ulonglong2 wb = *(const ulonglong2*)&zw1s[k * HC + j1];
                #pragma unroll
                for (int t = 0; t < 8; t++) {
                    float sv = ((const float*)&s4[t])[kk];
                    u64 sp = pack2(sv, sv);
                    ha[t][0] = fma2(sp, wa.x, ha[t][0]);
                    ha[t][1] = fma2(sp, wa.y, ha[t][1]);
                    ha[t][2] = fma2(sp, wb.x, ha[t][2]);
                    ha[t][3] = fma2(sp, wb.y, ha[t][3]);
                }
            }
        }
        // relu + store h (node-major)
        #pragma unroll
        for (int t = 0; t < 8; t++) {
            int nt = nrow0 + 4 * t;
            float4 v0, v1; float x, y;
            unpack2(ha[t][0], x, y); v0.x = fmaxf(x,0.f); v0.y = fmaxf(y,0.f);
            unpack2(ha[t][1], x, y); v0.z = fmaxf(x,0.f); v0.w = fmaxf(y,0.f);
            unpack2(ha[t][2], x, y); v1.x = fmaxf(x,0.f); v1.y = fmaxf(y,0.f);
            unpack2(ha[t][3], x, y); v1.z = fmaxf(x,0.f); v1.w = fmaxf(y,0.f);
            *(float4*)&hbuf[nt * HS + j0] = v0;
            *(float4*)&hbuf[nt * HS + j1] = v1;
        }
        __syncthreads();

        // ================= OUT phase (j-quarter q = jw) =================
        u64 acc[8][2];
        #pragma unroll
        for (int t = 0; t < 8; t++) { acc[t][0] = 0ull; acc[t][1] = 0ull; }
        #pragma unroll 2
        for (int j4 = 0; j4 < 16; j4++) {
            int jb = jw * 64 + j4 * 4;
            ulonglong2 w20 = *(const ulonglong2*)&w2s[(jb + 0) * OC + jg * 4];
            ulonglong2 w21 = *(const ulonglong2*)&w2s[(jb + 1) * OC + jg * 4];
            ulonglong2 w22 = *(const ulonglong2*)&w2s[(jb + 2) * OC + jg * 4];
            ulonglong2 w23 = *(const ulonglong2*)&w2s[(jb + 3) * OC + jg * 4];
            #pragma unroll
            for (int t = 0; t < 8; t++) {
                int nt = nrow0 + 4 * t;
                float4 hv = *(const float4*)&hbuf[nt * HS + jb];
                u64 h0 = pack2(hv.x, hv.x), h1 = pack2(hv.y, hv.y);
                u64 h2 = pack2(hv.z, hv.z), h3 = pack2(hv.w, hv.w);
                acc[t][0] = fma2(h0, w20.x, acc[t][0]);
                acc[t][1] = fma2(h0, w20.y, acc[t][1]);
                acc[t][0] = fma2(h1, w21.x, acc[t][0]);
                acc[t][1] = fma2(h1, w21.y, acc[t][1]);
                acc[t][0] = fma2(h2, w22.x, acc[t][0]);
                acc[t][1] = fma2(h2, w22.y, acc[t][1]);
                acc[t][0] = fma2(h3, w23.x, acc[t][0]);
                acc[t][1] = fma2(h3, w23.y, acc[t][1]);
            }
        }
        // store partials
        #pragma unroll
        for (int t = 0; t < 8; t++) {
            int nt = nrow0 + 4 * t;
            float4 v;
            unpack2(acc[t][0], v.x, v.y);
            unpack2(acc[t][1], v.z, v.w);
            *(float4*)&pbuf[(jw * CHUNK + nt) * PS + jg * 4] = v;
        }
        __syncthreads();

        // final: sum 4 quarters + b2, store (512 float4, 2 per thread)
        #pragma unroll
        for (int e = 0; e < 2; e++) {
            int idx = e * 256 + tid;
            int nn = idx >> 3, oo = (idx & 7) * 4;
            int nid = nids[nn];
            if (nid >= 0) {
                float4 r  = *(const float4*)&pbuf[(0 * CHUNK + nn) * PS + oo];
                float4 p1 = *(const float4*)&pbuf[(1 * CHUNK + nn) * PS + oo];
                float4 p2 = *(const float4*)&pbuf[(2 * CHUNK + nn) * PS + oo];
                float4 p3 = *(const float4*)&pbuf[(3 * CHUNK + nn) * PS + oo];
                r.x += p1.x + p2.x + p3.x + b2[oo + 0];
                r.y += p1.y + p2.y + p3.y + b2[oo + 1];
                r.z += p1.z + p2.z + p3.z + b2[oo + 2];
                r.w += p1.w + p2.w + p3.w + b2[oo + 3];
                *(float4*)(out + (size_t)nid * OC + oo) = r;
            }
        }
    }
}

// ---------------- launch ----------------------------------------------------
extern "C" void kernel_launch(void* const* d_in, const int* in_sizes, int n_in,
                              void* d_out, int out_size) {
    const float* z     = (const float*)d_in[0];
    const float* s     = (const float*)d_in[1];
    const int*   batch = (const int*)d_in[2];   // JAX x64 disabled -> int32
    const float* W1    = (const float*)d_in[3];
    const float* b1    = (const float*)d_in[4];
    const float* W2    = (const float*)d_in[5];
    const float* b2    = (const float*)d_in[6];
    float*       out   = (float*)d_out;

    int n = in_sizes[2];
    int B = in_sizes[0] / (KC * LC);
    int zb = (B * KC + 15) / 16;

    cudaFuncSetAttribute(prep_kernel,
        cudaFuncAttributeMaxDynamicSharedMemorySize, ZW1_SMEM);
    cudaFuncSetAttribute(main_kernel,
        cudaFuncAttributeMaxDynamicSharedMemorySize, MAIN_SMEM);

    prep_kernel<<<zb + NB, 256, ZW1_SMEM>>>(z, W1, batch, n, B, zb);
    scan_kernel<<<1, BMAX>>>();
    scatter_kernel<<<NB, 256>>>(batch, n, B);
    main_kernel<<<B * CPG, 256, MAIN_SMEM>>>(s, W2, b1, b2, out, B);
}

// round 14
// speedup vs baseline: 2.0349x; 1.1063x over previous
#include <cuda_runtime.h>

#define KC 32
#define LC 64
#define HC 256
#define OC 32
#define BMAX 256
#define NMAX 100000
#define NB 128            // histogram / scatter blocks
#define CPG 4             // CTAs per graph
#define CHUNK 64          // nodes per CTA chunk
#define SS 36             // ss row stride (floats)
#define HS 264            // hbuf row stride (floats)
#define PS 36             // pbuf row stride (floats)

#define ZW1_SMEM ((LC*HC + 4*LC) * 4)
// zw1s + ss + hbuf (pbuf aliases hbuf) + nids
#define MAIN_FLOATS (KC*HC + CHUNK*SS + CHUNK*HS)
#define MAIN_SMEM (MAIN_FLOATS*4 + CHUNK*4)

typedef unsigned long long u64;

__device__ __forceinline__ u64 fma2(u64 a, u64 b, u64 c) {
    u64 d;
    asm("fma.rn.f32x2 %0, %1, %2, %3;" : "=l"(d) : "l"(a), "l"(b), "l"(c));
    return d;
}
__device__ __forceinline__ u64 pack2(float lo, float hi) {
    u64 d;
    asm("mov.b64 %0, {%1, %2};" : "=l"(d) : "f"(lo), "f"(hi));
    return d;
}
__device__ __forceinline__ void unpack2(u64 v, float& lo, float& hi) {
    asm("mov.b64 {%0, %1}, %2;" : "=f"(lo), "=f"(hi) : "l"(v));
}

// ---------------- device scratch ------------------------------------------
__device__ float g_zw1[BMAX * KC * HC];    // 8 MB: z @ W1
__device__ int   g_perm[NMAX];
__device__ int   g_hist[BMAX];
__device__ int   g_cnt[BMAX];
__device__ int   g_binstart[BMAX];
__device__ int   g_cursor[BMAX];
__device__ int   g_bh[NB * BMAX];          // per-block histograms

// ---------------- 1. prep: zW1 GEMM | per-block hist -----------------------
__global__ void prep_kernel(const float* __restrict__ z,
                            const float* __restrict__ W1,
                            const int* __restrict__ batch,
                            int n, int B, int zb) {
    int tid = threadIdx.x;
    int bx = blockIdx.x;

    if (bx >= zb) {
        __shared__ int sh[BMAX];
        int blk = bx - zb;
        sh[tid] = 0;
        __syncthreads();
        int span = (n + NB - 1) / NB;
        int lo = blk * span, hi = min(n, lo + span);
        for (int i = lo + tid; i < hi; i += 256) {
            int b = batch[i];
            if (b >= 0 && b < B) atomicAdd(&sh[b], 1);
        }
        __syncthreads();
        g_bh[blk * BMAX + tid] = sh[tid];
        if (sh[tid]) atomicAdd(&g_hist[tid], sh[tid]);
        return;
    }
    extern __shared__ __align__(16) float sm[];
    float* w1s = sm;              // LC*HC
    float* zs  = sm + LC * HC;    // 4*LC

    for (int i = tid; i < (LC * HC) / 4; i += 256)
        ((float4*)w1s)[i] = ((const float4*)W1)[i];

    int rows = zb * 16;
    int row0 = bx * 16;
    for (int g = 0; g < 4; g++) {
        int rbase = row0 + g * 4;
        __syncthreads();
        int rr = tid >> 6, ll = tid & 63;
        if (rbase + rr < rows)
            zs[rr * LC + ll] = z[(size_t)(rbase + rr) * LC + ll];
        __syncthreads();

        float a0 = 0.f, a1 = 0.f, a2 = 0.f, a3 = 0.f;
        #pragma unroll
        for (int l = 0; l < LC; l++) {
            float w = w1s[l * HC + tid];
            a0 += zs[0 * LC + l] * w;
            a1 += zs[1 * LC + l] * w;
            a2 += zs[2 * LC + l] * w;
            a3 += zs[3 * LC + l] * w;
        }
        if (rbase + 3 < rows) {
            g_zw1[(size_t)(rbase + 0) * HC + tid] = a0;
            g_zw1[(size_t)(rbase + 1) * HC + tid] = a1;
            g_zw1[(size_t)(rbase + 2) * HC + tid] = a2;
            g_zw1[(size_t)(rbase + 3) * HC + tid] = a3;
        }
    }
}

// ---------------- 2. scan ---------------------------------------------------
__global__ void scan_kernel() {
    __shared__ int tmp[BMAX];
    int tid = threadIdx.x;
    int v0 = g_hist[tid];
    g_cnt[tid]  = v0;
    g_hist[tid] = 0;               // idempotent across graph replays
    tmp[tid] = v0;
    __syncthreads();
    for (int d = 1; d < BMAX; d <<= 1) {
        int v = (tid >= d) ? tmp[tid - d] : 0;
        __syncthreads();
        tmp[tid] += v;
        __syncthreads();
    }
    int start = tmp[tid] - v0;
    g_binstart[tid] = start;
    g_cursor[tid]   = start;
}

// ---------------- 3. scatter ------------------------------------------------
__global__ void scatter_kernel(const int* __restrict__ batch, int n, int B) {
    __shared__ int cur[BMAX];
    int tid = threadIdx.x, blk = blockIdx.x;
    int mine = g_bh[blk * BMAX + tid];
    cur[tid] = mine ? atomicAdd(&g_cursor[tid], mine) : 0;   // spread atomics
    __syncthreads();
    int span = (n + NB - 1) / NB;
    int lo = blk * span, hi = min(n, lo + span);
    for (int i = lo + tid; i < hi; i += 256) {
        int b = batch[i];
        if (b < 0 || b >= B) continue;
        int pos = atomicAdd(&cur[b], 1);    // smem atomic
        g_perm[pos] = i;
    }
}

// ---------------- 4. main fused kernel --------------------------------------
// Same tile geometry as R13 (the thing that worked), but occupancy 2:
//  - W2 read via __ldg from global (L1-resident), no smem stage
//  - pbuf aliases hbuf (extra sync separates reads from partial writes)
// H   phase: warp(nh, jw): 32n x 64j.  lane(ng, jg): 8n x 8j.
// OUT phase: warp(nh, q=jw): 32n x 32o over 64j. lane(ng, og=jg): 8n x 4o.
__global__ __launch_bounds__(256, 2)
void main_kernel(const float* __restrict__ s, const float* __restrict__ W2,
                 const float* __restrict__ b1, const float* __restrict__ b2,
                 float* __restrict__ out, int B) {
    extern __shared__ __align__(16) float sm[];
    float* zw1s = sm;                        // [k][j]  32x256 = 8192 fl
    float* ss   = zw1s + KC * HC;            // [n][SS]         2304 fl
    float* hbuf = ss + CHUNK * SS;           // [n][HS]        16896 fl
    float* pbuf = hbuf;                      // alias (sync-separated)
    int*   nids = (int*)(hbuf + CHUNK * HS);

    int tid = threadIdx.x;
    int b   = blockIdx.x % B;
    int c0  = blockIdx.x / B;
    int cnt = g_cnt[b];
    if (c0 * CHUNK >= cnt) return;
    int start = g_binstart[b];

    // prologue: stage per-graph zW1
    const float4* zw1g = (const float4*)(g_zw1 + (size_t)b * KC * HC);
    #pragma unroll
    for (int i = 0; i < 8; i++)
        ((float4*)zw1s)[tid + i * 256] = zw1g[tid + i * 256];

    int w = tid >> 5, lane = tid & 31;
    int nh = w & 1;                  // node half (both phases)
    int jw = w >> 1;                 // H: j-group   OUT: j-quarter q
    int ng = lane >> 3;              // node sub-group
    int jg = lane & 7;               // H: j sub     OUT: o-quad
    int j0 = jw * 64 + jg * 4;
    int j1 = j0 + 32;
    int nrow0 = nh * 32 + ng;        // node = nrow0 + 4*t

    // b1 bias quads in registers (packed)
    u64 bq[4];
    {
        float4 v = *(const float4*)&b1[j0];
        bq[0] = pack2(v.x, v.y); bq[1] = pack2(v.z, v.w);
        v = *(const float4*)&b1[j1];
        bq[2] = pack2(v.x, v.y); bq[3] = pack2(v.z, v.w);
    }

    for (int c = c0; c * CHUNK < cnt; c += CPG) {
        int nbase = c * CHUNK;
        __syncthreads();             // protects ss/nids/hbuf reuse (+prologue)
        // stage nids + s rows (512 float4, 2 per thread)
        #pragma unroll
        for (int e = 0; e < 2; e++) {
            int idx = e * 256 + tid;
            int i = idx >> 3, qq = idx & 7;
            int gi = nbase + i;
            int nid = (gi < cnt) ? g_perm[start + gi] : -1;
            if (qq == 0) nids[i] = nid;
            float4 v = make_float4(0.f, 0.f, 0.f, 0.f);
            if (nid >= 0) v = ((const float4*)(s + (size_t)nid * KC))[qq];
            *(float4*)&ss[i * SS + qq * 4] = v;
        }
        __syncthreads();

        // ================= H phase =================
        u64 ha[8][4];
        #pragma unroll
        for (int t = 0; t < 8; t++) {
            ha[t][0] = bq[0]; ha[t][1] = bq[1];
            ha[t][2] = bq[2]; ha[t][3] = bq[3];
        }
        #pragma unroll
        for (int kg = 0; kg < 8; kg++) {
            float4 s4[8];
            #pragma unroll
            for (int t = 0; t < 8; t++)
                s4[t] = *(const float4*)&ss[(nrow0 + 4 * t) * SS + kg * 4];
            #pragma unroll
            for (int kk = 0; kk < 4; kk++) {
                int k = kg * 4 + kk;
                ulonglong2 wa = *(const ulonglong2*)&zw1s[k * HC + j0];
                ulonglong2 wb = *(const ulonglong2*)&zw1s[k * HC + j1];
                #pragma unroll
                for (int t = 0; t < 8; t++) {
                    float sv = ((const float*)&s4[t])[kk];
                    u64 sp = pack2(sv, sv);
                    ha[t][0] = fma2(sp, wa.x, ha[t][0]);
                    ha[t][1] = fma2(sp, wa.y, ha[t][1]);
                    ha[t][2] = fma2(sp, wb.x, ha[t][2]);
                    ha[t][3] = fma2(sp, wb.y, ha[t][3]);
                }
            }
        }
        // relu + store h (node-major)
        #pragma unroll
        for (int t = 0; t < 8; t++) {
            int nt = nrow0 + 4 * t;
            float4 v0, v1; float x, y;
            unpack2(ha[t][0], x, y); v0.x = fmaxf(x,0.f); v0.y = fmaxf(y,0.f);
            unpack2(ha[t][1], x, y); v0.z = fmaxf(x,0.f); v0.w = fmaxf(y,0.f);
            unpack2(ha[t][2], x, y); v1.x = fmaxf(x,0.f); v1.y = fmaxf(y,0.f);
            unpack2(ha[t][3], x, y); v1.z = fmaxf(x,0.f); v1.w = fmaxf(y,0.f);
            *(float4*)&hbuf[nt * HS + j0] = v0;
            *(float4*)&hbuf[nt * HS + j1] = v1;
        }
        __syncthreads();

        // ================= OUT phase (j-quarter q = jw) =================
        u64 acc[8][2];
        #pragma unroll
        for (int t = 0; t < 8; t++) { acc[t][0] = 0ull; acc[t][1] = 0ull; }
        #pragma unroll 2
        for (int j4 = 0; j4 < 16; j4++) {
            int jb = jw * 64 + j4 * 4;
            // W2 from global: 128B-coalesced per row-quad, L1-resident
            ulonglong2 w20 = __ldg((const ulonglong2*)(W2 + (jb + 0) * OC + jg * 4));
            ulonglong2 w21 = __ldg((const ulonglong2*)(W2 + (jb + 1) * OC + jg * 4));
            ulonglong2 w22 = __ldg((const ulonglong2*)(W2 + (jb + 2) * OC + jg * 4));
            ulonglong2 w23 = __ldg((const ulonglong2*)(W2 + (jb + 3) * OC + jg * 4));
            #pragma unroll
            for (int t = 0; t < 8; t++) {
                int nt = nrow0 + 4 * t;
                float4 hv = *(const float4*)&hbuf[nt * HS + jb];
                u64 h0 = pack2(hv.x, hv.x), h1 = pack2(hv.y, hv.y);
                u64 h2 = pack2(hv.z, hv.z), h3 = pack2(hv.w, hv.w);
                acc[t][0] = fma2(h0, w20.x, acc[t][0]);
                acc[t][1] = fma2(h0, w20.y, acc[t][1]);
                acc[t][0] = fma2(h1, w21.x, acc[t][0]);
                acc[t][1] = fma2(h1, w21.y, acc[t][1]);
                acc[t][0] = fma2(h2, w22.x, acc[t][0]);
                acc[t][1] = fma2(h2, w22.y, acc[t][1]);
                acc[t][0] = fma2(h3, w23.x, acc[t][0]);
                acc[t][1] = fma2(h3, w23.y, acc[t][1]);
            }
        }
        __syncthreads();     // all hbuf reads done before pbuf (alias) writes
        // store partials into aliased region
        #pragma unroll
        for (int t = 0; t < 8; t++) {
            int nt = nrow0 + 4 * t;
            float4 v;
            unpack2(acc[t][0], v.x, v.y);
            unpack2(acc[t][1], v.z, v.w);
            *(float4*)&pbuf[(jw * CHUNK + nt) * PS + jg * 4] = v;
        }
        __syncthreads();

        // final: sum 4 quarters + b2, store (512 float4, 2 per thread)
        #pragma unroll
        for (int e = 0; e < 2; e++) {
            int idx = e * 256 + tid;
            int nn = idx >> 3, oo = (idx & 7) * 4;
            int nid = nids[nn];
            if (nid >= 0) {
                float4 r  = *(const float4*)&pbuf[(0 * CHUNK + nn) * PS + oo];
                float4 p1 = *(const float4*)&pbuf[(1 * CHUNK + nn) * PS + oo];
                float4 p2 = *(const float4*)&pbuf[(2 * CHUNK + nn) * PS + oo];
                float4 p3 = *(const float4*)&pbuf[(3 * CHUNK + nn) * PS + oo];
                float4 bb = __ldg((const float4*)(b2 + oo));
                r.x += p1.x + p2.x + p3.x + bb.x;
                r.y += p1.y + p2.y + p3.y + bb.y;
                r.z += p1.z + p2.z + p3.z + bb.z;
                r.w += p1.w + p2.w + p3.w + bb.w;
                *(float4*)(out + (size_t)nid * OC + oo) = r;
            }
        }
    }
}

// ---------------- launch ----------------------------------------------------
extern "C" void kernel_launch(void* const* d_in, const int* in_sizes, int n_in,
                              void* d_out, int out_size) {
    const float* z     = (const float*)d_in[0];
    const float* s     = (const float*)d_in[1];
    const int*   batch = (const int*)d_in[2];   // JAX x64 disabled -> int32
    const float* W1    = (const float*)d_in[3];
    const float* b1    = (const float*)d_in[4];
    const float* W2    = (const float*)d_in[5];
    const float* b2    = (const float*)d_in[6];
    float*       out   = (float*)d_out;

    int n = in_sizes[2];
    int B = in_sizes[0] / (KC * LC);
    int zb = (B * KC + 15) / 16;

    cudaFuncSetAttribute(prep_kernel,
        cudaFuncAttributeMaxDynamicSharedMemorySize, ZW1_SMEM);
    cudaFuncSetAttribute(main_kernel,
        cudaFuncAttributeMaxDynamicSharedMemorySize, MAIN_SMEM);

    prep_kernel<<<zb + NB, 256, ZW1_SMEM>>>(z, W1, batch, n, B, zb);
    scan_kernel<<<1, BMAX>>>();
    scatter_kernel<<<NB, 256>>>(batch, n, B);
    main_kernel<<<B * CPG, 256, MAIN_SMEM>>>(s, W2, b1, b2, out, B);
}